// round 13
// baseline (speedup 1.0000x reference)
#include <cuda_runtime.h>
#include <cuda_bf16.h>
#include <math.h>
#include <stdint.h>

#define HOx 64
#define WOx 64
#define DIMX 128
#define BATCH 4
#define NP (HOx*WOx)            /* 4096  */
#define NTOK (BATCH*NP)         /* 16384 */
#define NTOKIN (BATCH*128*128)  /* 65536 */

// ---------------- scratch (static device globals; no runtime alloc) ----------------
__device__ float g_k [(size_t)NTOKIN*DIMX];
__device__ float g_v [(size_t)NTOKIN*DIMX];
__device__ float g_q  [(size_t)NTOK*DIMX];
__device__ float g_seed[(size_t)NTOK*DIMX];
__device__ float g_h2[(size_t)NTOK*DIMX];
__device__ float g_cs[NTOK];
__device__ float g_wc[9*DIMX*DIMX];
__device__ int   g_rows[9*NTOK];
// 16 weight images, each: 16384 bf16 hi + 16384 bf16 lo, row-major [n][k]
__device__ __nv_bfloat16 g_wimg[16*32768];
// pre-split activation images: hi plane then lo plane
__device__ __nv_bfloat16 g_xr  [2*(size_t)NTOKIN*DIMX];  // raw x
__device__ __nv_bfloat16 g_xl  [2*(size_t)NTOKIN*DIMX];  // LN_in(x)
__device__ __nv_bfloat16 g_xor_[2*(size_t)NTOK*DIMX];    // raw xout (post-upd)
__device__ __nv_bfloat16 g_xol [2*(size_t)NTOK*DIMX];    // LN_out(xout)
__device__ __nv_bfloat16 g_hb  [2*(size_t)NTOK*2*DIMX];  // gelu(h)

// ---------------- PTX helpers ----------------
__device__ __forceinline__ uint32_t smem_u32(const void* p) {
    uint32_t a;
    asm("{ .reg .u64 t; cvta.to.shared.u64 t, %1; cvt.u32.u64 %0, t; }" : "=r"(a) : "l"(p));
    return a;
}
__device__ __forceinline__ void ldsm4(uint32_t addr, uint32_t& r0, uint32_t& r1, uint32_t& r2, uint32_t& r3)
{
    asm volatile("ldmatrix.sync.aligned.m8n8.x4.shared.b16 {%0,%1,%2,%3}, [%4];"
                 : "=r"(r0), "=r"(r1), "=r"(r2), "=r"(r3) : "r"(addr));
}
__device__ __forceinline__ void mma16816(float* c, const uint32_t* a,
                                         uint32_t b0, uint32_t b1)
{
    asm volatile("mma.sync.aligned.m16n8k16.row.col.f32.bf16.bf16.f32 "
                 "{%0,%1,%2,%3}, {%4,%5,%6,%7}, {%8,%9}, {%0,%1,%2,%3};"
                 : "+f"(c[0]), "+f"(c[1]), "+f"(c[2]), "+f"(c[3])
                 : "r"(a[0]), "r"(a[1]), "r"(a[2]), "r"(a[3]), "r"(b0), "r"(b1));
}
__device__ __forceinline__ void cp16(uint32_t dst, const void* src)
{
    asm volatile("cp.async.ca.shared.global [%0], [%1], 16;" :: "r"(dst), "l"(src));
}
__device__ __forceinline__ void cp16z(uint32_t dst, const void* src, int sz)
{
    asm volatile("cp.async.ca.shared.global [%0], [%1], 16, %2;" :: "r"(dst), "l"(src), "r"(sz));
}
#define CP_COMMIT() asm volatile("cp.async.commit_group;" ::: "memory")
#define CP_WAIT0()  asm volatile("cp.async.wait_group 0;" ::: "memory")

__device__ __forceinline__ uint32_t packbf(float a, float b)
{
    __nv_bfloat16 x = __float2bfloat16(a), y = __float2bfloat16(b);
    return (uint32_t)__bfloat16_as_ushort(x) | ((uint32_t)__bfloat16_as_ushort(y) << 16);
}
__device__ __forceinline__ void split4(float4 v, uint2& hp, uint2& lp)
{
    __nv_bfloat16 h0 = __float2bfloat16(v.x), h1 = __float2bfloat16(v.y);
    __nv_bfloat16 h2 = __float2bfloat16(v.z), h3 = __float2bfloat16(v.w);
    hp.x = (uint32_t)__bfloat16_as_ushort(h0) | ((uint32_t)__bfloat16_as_ushort(h1) << 16);
    hp.y = (uint32_t)__bfloat16_as_ushort(h2) | ((uint32_t)__bfloat16_as_ushort(h3) << 16);
    lp.x = packbf(v.x - __bfloat162float(h0), v.y - __bfloat162float(h1));
    lp.y = packbf(v.z - __bfloat162float(h2), v.w - __bfloat162float(h3));
}

// ---------------- prep: conv weight transpose + conv row-gather table ----------------
__global__ void prep_conv(const float* __restrict__ conv_w)
{
    int i = blockIdx.x * blockDim.x + threadIdx.x;
    if (i < 9*DIMX*DIMX) {
        int kk = i / (DIMX*DIMX);
        int r  = i % (DIMX*DIMX);
        int c  = r / DIMX, dout = r % DIMX;
        int ky = kk / 3, kx = kk % 3;
        g_wc[i] = conv_w[((dout*DIMX + c)*3 + ky)*3 + kx];
    }
    if (i < 9*NTOK) {
        int kk = i / NTOK;
        int m  = i % NTOK;
        int b  = m >> 12, p = m & 4095;
        int ho = p >> 6, wo = p & 63;
        int ky = kk / 3, kx = kk % 3;
        int y = 2*ho - 1 + ky;
        int x = 2*wo - 1 + kx;
        g_rows[i] = (y >= 0 && y < 128 && x >= 0 && x < 128) ? (b*16384 + y*128 + x) : -1;
    }
}

// ---------------- prep: 16 pre-split B images, row-major [n][k] (W transposed) ----------------
__global__ void prep_img(const float* __restrict__ k_w, const float* __restrict__ v_w,
                         const float* __restrict__ q_w, const float* __restrict__ mlp_w1,
                         const float* __restrict__ mlp_w2)
{
    int e   = blockIdx.x * blockDim.x + threadIdx.x; // 0..16383
    int img = blockIdx.y;                            // 0..15
    int k = e >> 7, n = e & 127;

    const float* src; int ldn, k0, n0;
    if      (img == 0) { src = k_w;    ldn = 128; k0 = 0;   n0 = 0;   }
    else if (img == 1) { src = v_w;    ldn = 128; k0 = 0;   n0 = 0;   }
    else if (img == 2) { src = q_w;    ldn = 128; k0 = 0;   n0 = 0;   }
    else if (img == 3) { src = mlp_w1; ldn = 256; k0 = 0;   n0 = 0;   }
    else if (img == 4) { src = mlp_w1; ldn = 256; k0 = 0;   n0 = 128; }
    else if (img == 5) { src = mlp_w2; ldn = 128; k0 = 0;   n0 = 0;   }
    else if (img == 6) { src = mlp_w2; ldn = 128; k0 = 128; n0 = 0;   }
    else               { src = g_wc + (img - 7)*DIMX*DIMX; ldn = 128; k0 = 0; n0 = 0; }

    float w = src[(size_t)(k0 + k) * ldn + n0 + n];
    __nv_bfloat16 hi = __float2bfloat16(w);
    __nv_bfloat16 lo = __float2bfloat16(w - __bfloat162float(hi));
    __nv_bfloat16* dst = g_wimg + (size_t)img * 32768;
    dst[n*128 + k]         = hi;
    dst[16384 + n*128 + k] = lo;
}

// ---------------- split x: raw split + LN_in split (warp per row) ----------------
__global__ void split_x(const float* __restrict__ x,
                        const float* __restrict__ g, const float* __restrict__ b)
{
    int row  = (blockIdx.x * blockDim.x + threadIdx.x) >> 5;
    int lane = threadIdx.x & 31;
    float4 v = ((const float4*)(x + (size_t)row * DIMX))[lane];
    uint2 hp, lp;
    split4(v, hp, lp);
    size_t off = (size_t)row * DIMX + lane*4;
    *(uint2*)((uint16_t*)g_xr + off)                          = hp;
    *(uint2*)((uint16_t*)g_xr + (size_t)NTOKIN*DIMX + off)    = lp;
    float s  = v.x + v.y + v.z + v.w;
    float sq = v.x*v.x + v.y*v.y + v.z*v.z + v.w*v.w;
    #pragma unroll
    for (int o = 16; o > 0; o >>= 1) {
        s  += __shfl_xor_sync(0xffffffffu, s,  o);
        sq += __shfl_xor_sync(0xffffffffu, sq, o);
    }
    float mu  = s * (1.0f/DIMX);
    float var = sq * (1.0f/DIMX) - mu*mu;
    float rs  = rsqrtf(var + 1e-5f);
    float4 g4 = ((const float4*)g)[lane];
    float4 b4 = ((const float4*)b)[lane];
    float4 t;
    t.x = (v.x - mu)*rs*g4.x + b4.x;
    t.y = (v.y - mu)*rs*g4.y + b4.y;
    t.z = (v.z - mu)*rs*g4.z + b4.z;
    t.w = (v.w - mu)*rs*g4.w + b4.w;
    split4(t, hp, lp);
    *(uint2*)((uint16_t*)g_xl + off)                          = hp;
    *(uint2*)((uint16_t*)g_xl + (size_t)NTOKIN*DIMX + off)    = lp;
}

// ---------------- ln2: xout = LN(in) (mode 0) or xout += LN(in) (mode 1);
//                  then write LN_out(xout) split for next q-gemm ----------------
__global__ void ln2_kernel(const float* __restrict__ in, float* __restrict__ xout,
                           const float* __restrict__ g, const float* __restrict__ b,
                           int mode)
{
    int row  = (blockIdx.x * blockDim.x + threadIdx.x) >> 5;
    int lane = threadIdx.x & 31;
    float4 v = ((const float4*)(in + (size_t)row * DIMX))[lane];
    float s  = v.x + v.y + v.z + v.w;
    float sq = v.x*v.x + v.y*v.y + v.z*v.z + v.w*v.w;
    #pragma unroll
    for (int o = 16; o > 0; o >>= 1) {
        s  += __shfl_xor_sync(0xffffffffu, s,  o);
        sq += __shfl_xor_sync(0xffffffffu, sq, o);
    }
    float mu  = s * (1.0f/DIMX);
    float var = sq * (1.0f/DIMX) - mu*mu;
    float rs  = rsqrtf(var + 1e-5f);
    float4 g4 = ((const float4*)g)[lane];
    float4 b4 = ((const float4*)b)[lane];
    float4 t;
    t.x = (v.x - mu)*rs*g4.x + b4.x;
    t.y = (v.y - mu)*rs*g4.y + b4.y;
    t.z = (v.z - mu)*rs*g4.z + b4.z;
    t.w = (v.w - mu)*rs*g4.w + b4.w;
    float4* op = (float4*)(xout + (size_t)row * DIMX);
    if (mode) {
        float4 e = op[lane];
        t.x += e.x; t.y += e.y; t.z += e.z; t.w += e.w;
    }
    op[lane] = t;
    // second LN on the new xout row
    s  = t.x + t.y + t.z + t.w;
    sq = t.x*t.x + t.y*t.y + t.z*t.z + t.w*t.w;
    #pragma unroll
    for (int o = 16; o > 0; o >>= 1) {
        s  += __shfl_xor_sync(0xffffffffu, s,  o);
        sq += __shfl_xor_sync(0xffffffffu, sq, o);
    }
    mu  = s * (1.0f/DIMX);
    var = sq * (1.0f/DIMX) - mu*mu;
    rs  = rsqrtf(var + 1e-5f);
    float4 u;
    u.x = (t.x - mu)*rs*g4.x + b4.x;
    u.y = (t.y - mu)*rs*g4.y + b4.y;
    u.z = (t.z - mu)*rs*g4.z + b4.z;
    u.w = (t.w - mu)*rs*g4.w + b4.w;
    uint2 hp, lp;
    split4(u, hp, lp);
    size_t off = (size_t)row * DIMX + lane*4;
    *(uint2*)((uint16_t*)g_xol + off)                        = hp;
    *(uint2*)((uint16_t*)g_xol + (size_t)NTOK*DIMX + off)    = lp;
}

__device__ __forceinline__ float gelu_exact(float x)
{
    return 0.5f * x * (1.0f + erff(x * 0.70710678118654752f));
}

// ---------------- tensor-core GEMM: 64x64 CTA tile, 3 CTAs/SM ----------------
// 256 threads, 8 warps (2x4), warp tile 32x16, frag-cached 3-pass hi/lo.
#define TSTRIDE 136
#define TILE_A (64*TSTRIDE*2)      /* 17408 bytes */
#define TILE_B (64*TSTRIDE*2)      /* 17408 bytes */
#define TG_SMEM (2*TILE_A + 2*TILE_B)  /* 69632 */

__global__ __launch_bounds__(256, 3)
void tgemm2(int M, int Krow, int nseg,
            const __nv_bfloat16* __restrict__ Aimg, size_t Aplane,
            const int* __restrict__ rowtab,
            const __nv_bfloat16* __restrict__ Bimg,
            float* __restrict__ C, int ldc,
            const float* __restrict__ bias, int act,
            __nv_bfloat16* OutSplit, size_t Oplane)
{
    extern __shared__ char smem[];
    const uint32_t sb = smem_u32(smem);
    const uint32_t A_HI = sb, A_LO = sb + TILE_A, B_HI = sb + 2*TILE_A, B_LO = sb + 2*TILE_A + TILE_B;

    const int tid = threadIdx.x, wid = tid >> 5, lane = tid & 31;
    const int brow = blockIdx.y * 64;
    const int bcol = blockIdx.x * 64;
    const int cb128  = blockIdx.x >> 1;         // which 128-col weight image block
    const int rowoff = (blockIdx.x & 1) * 64;   // row offset inside that image
    const int rowbase = (wid & 1) * 32;         // warp tile 32 rows
    const int colbase = (wid >> 1) * 16;        //           x 16 cols

    float acc[2][2][4];
    #pragma unroll
    for (int mt = 0; mt < 2; mt++)
        #pragma unroll
        for (int nt = 0; nt < 2; nt++)
            #pragma unroll
            for (int r = 0; r < 4; r++) acc[mt][nt][r] = 0.0f;

    const uint32_t aAddr0 = (uint32_t)((rowbase + (lane & 15)) * (TSTRIDE*2) + (lane >> 4) * 16);
    const uint32_t bAddr0 = (uint32_t)((colbase + (lane & 7))  * (TSTRIDE*2) + (lane >> 3) * 16);

    for (int seg = 0; seg < nseg; seg++) {
        if (seg) __syncthreads();

        // ---- A tile: 2048 16B chunks (hi+lo), cp.async with zero-fill for OOB rows ----
        {
            const int acol = rowtab ? 0 : seg * 128;
            #pragma unroll
            for (int i = 0; i < 8; i++) {
                int idx   = i * 256 + tid;          // 0..2047
                int plane = idx >> 10;              // 0 hi, 1 lo
                int r     = (idx >> 4) & 63;
                int ch    = idx & 15;
                int srow  = rowtab ? rowtab[(size_t)seg * M + brow + r] : (brow + r);
                uint32_t dst = (plane ? A_LO : A_HI) + (uint32_t)(r * (TSTRIDE*2) + ch * 16);
                const __nv_bfloat16* src = Aimg + (size_t)plane * Aplane
                                         + (size_t)(srow < 0 ? 0 : srow) * Krow + acol + ch * 8;
                cp16z(dst, src, srow < 0 ? 0 : 16);
            }
        }
        // ---- B tile: 64 rows x 128k x 2 planes = 2048 16B chunks ----
        {
            const __nv_bfloat16* Bseg = Bimg + ((size_t)(cb128 * nseg + seg)) * 32768;
            #pragma unroll
            for (int i = 0; i < 8; i++) {
                int idx   = i * 256 + tid;          // 0..2047
                int plane = idx >> 10;
                int r     = (idx >> 4) & 63;
                int ch    = idx & 15;
                uint32_t dst = (plane ? B_LO : B_HI) + (uint32_t)(r * (TSTRIDE*2) + ch * 16);
                cp16(dst, Bseg + plane * 16384 + (rowoff + r) * 128 + ch * 8);
            }
        }
        CP_COMMIT();
        CP_WAIT0();
        __syncthreads();

        // ---- cached fragments; 3 passes from registers ----
        #pragma unroll
        for (int kc = 0; kc < 4; kc++) {
            uint32_t bh[2][4], bl[2][4];
            #pragma unroll
            for (int nt = 0; nt < 2; nt++) {
                uint32_t boff = bAddr0 + nt*8*(TSTRIDE*2) + kc*64;
                ldsm4(B_HI + boff, bh[nt][0], bh[nt][1], bh[nt][2], bh[nt][3]);
                ldsm4(B_LO + boff, bl[nt][0], bl[nt][1], bl[nt][2], bl[nt][3]);
            }
            uint32_t ah[2][2][4], al[2][2][4];   // [half][mt]
            #pragma unroll
            for (int half = 0; half < 2; half++)
                #pragma unroll
                for (int mt = 0; mt < 2; mt++) {
                    uint32_t aoff = aAddr0 + mt*16*(TSTRIDE*2) + kc*64 + half*32;
                    ldsm4(A_HI + aoff, ah[half][mt][0], ah[half][mt][1], ah[half][mt][2], ah[half][mt][3]);
                    ldsm4(A_LO + aoff, al[half][mt][0], al[half][mt][1], al[half][mt][2], al[half][mt][3]);
                }
            #pragma unroll
            for (int half = 0; half < 2; half++)
                #pragma unroll
                for (int mt = 0; mt < 2; mt++)
                    #pragma unroll
                    for (int nt = 0; nt < 2; nt++)
                        mma16816(acc[mt][nt], ah[half][mt], bh[nt][half*2], bh[nt][half*2+1]);
            #pragma unroll
            for (int half = 0; half < 2; half++)
                #pragma unroll
                for (int mt = 0; mt < 2; mt++)
                    #pragma unroll
                    for (int nt = 0; nt < 2; nt++)
                        mma16816(acc[mt][nt], ah[half][mt], bl[nt][half*2], bl[nt][half*2+1]);
            #pragma unroll
            for (int half = 0; half < 2; half++)
                #pragma unroll
                for (int mt = 0; mt < 2; mt++)
                    #pragma unroll
                    for (int nt = 0; nt < 2; nt++)
                        mma16816(acc[mt][nt], al[half][mt], bh[nt][half*2], bh[nt][half*2+1]);
        }
    }

    // ---- epilogue ----
    #pragma unroll
    for (int mt = 0; mt < 2; mt++) {
        int r0 = brow + rowbase + mt*16 + (lane >> 2);
        #pragma unroll
        for (int nt = 0; nt < 2; nt++) {
            int c = bcol + colbase + nt*8 + (lane & 3)*2;
            float v0 = acc[mt][nt][0], v1 = acc[mt][nt][1];
            float v2 = acc[mt][nt][2], v3 = acc[mt][nt][3];
            if (bias) {
                float b0 = bias[c], b1 = bias[c+1];
                v0 += b0; v1 += b1; v2 += b0; v3 += b1;
            }
            if (act) {
                v0 = gelu_exact(v0); v1 = gelu_exact(v1);
                v2 = gelu_exact(v2); v3 = gelu_exact(v3);
            }
            if (OutSplit) {
                uint16_t* hi = (uint16_t*)OutSplit;
                uint16_t* lo = hi + Oplane;
                __nv_bfloat16 h0 = __float2bfloat16(v0), h1 = __float2bfloat16(v1);
                __nv_bfloat16 h2 = __float2bfloat16(v2), h3 = __float2bfloat16(v3);
                *(uint32_t*)(hi + (size_t)r0*ldc + c) =
                    (uint32_t)__bfloat16_as_ushort(h0) | ((uint32_t)__bfloat16_as_ushort(h1) << 16);
                *(uint32_t*)(lo + (size_t)r0*ldc + c) =
                    packbf(v0 - __bfloat162float(h0), v1 - __bfloat162float(h1));
                *(uint32_t*)(hi + (size_t)(r0+8)*ldc + c) =
                    (uint32_t)__bfloat16_as_ushort(h2) | ((uint32_t)__bfloat16_as_ushort(h3) << 16);
                *(uint32_t*)(lo + (size_t)(r0+8)*ldc + c) =
                    packbf(v2 - __bfloat162float(h2), v3 - __bfloat162float(h3));
            } else {
                *(float2*)(C + (size_t)r0 * ldc + c)     = make_float2(v0, v1);
                *(float2*)(C + (size_t)(r0+8) * ldc + c) = make_float2(v2, v3);
            }
        }
    }
}

// ---------------- attention: dots + softmax + eps, atomic col sums ----------------
__global__ __launch_bounds__(128)
void attn_kernel(const float* __restrict__ Kv, const float* __restrict__ Qv,
                 const float* __restrict__ rpb, const float* __restrict__ tau,
                 float* __restrict__ attn_out, float* __restrict__ colsums)
{
    int bp = blockIdx.x;
    int b = bp >> 12, p = bp & 4095;
    int h = p >> 6, w = p & 63;
    int hc = min(max(h,1),62), wc = min(max(w,1),62);

    __shared__ __align__(16) float q_sh[9][128];
    int tid = threadIdx.x;
    #pragma unroll
    for (int t = 0; t < 9; t++) {
        int np = (hc + t/3 - 1)*64 + (wc + t%3 - 1);
        q_sh[t][tid] = Qv[((size_t)(b<<12) + np)*DIMX + tid];
    }
    __syncthreads();

    int g = tid >> 5, lane = tid & 31;
    int tin = (2*h + (g>>1))*128 + 2*w + (g&1);
    float4 kv = *(const float4*)(Kv + ((size_t)(b*16384 + tin))*DIMX + lane*4);

    float myd = 0.0f;
    #pragma unroll
    for (int t = 0; t < 9; t++) {
        float4 qv = *(const float4*)(&q_sh[t][lane*4]);
        float d = kv.x*qv.x + kv.y*qv.y + kv.z*qv.z + kv.w*qv.w;
        #pragma unroll
        for (int o = 16; o > 0; o >>= 1) d += __shfl_xor_sync(0xffffffffu, d, o);
        if (lane == t) myd = d;
    }

    float scale = expf(*tau);
    float z = (lane < 9) ? (myd + rpb[g*9 + lane]) * scale : -1e30f;
    float m = z;
    #pragma unroll
    for (int o = 16; o > 0; o >>= 1) m = fmaxf(m, __shfl_xor_sync(0xffffffffu, m, o));
    float e = (lane < 9) ? expf(z - m) : 0.0f;
    float s = e;
    #pragma unroll
    for (int o = 16; o > 0; o >>= 1) s += __shfl_xor_sync(0xffffffffu, s, o);

    if (lane < 9) {
        float a = e / s + 1e-6f;
        attn_out[(((size_t)(b*4 + g))*4096 + p)*9 + lane] = a;
        int np = (hc + lane/3 - 1)*64 + (wc + lane%3 - 1);
        atomicAdd(&colsums[(b<<12) + np], a);
    }
}

// ---------------- column-normalize + weighted v gather; x_out += upd; raw split out ----
__global__ __launch_bounds__(128)
void upd_kernel(const float* __restrict__ attn_out, const float* __restrict__ colsums,
                const float* __restrict__ Vv, float* __restrict__ acol_out,
                float* __restrict__ x_out)
{
    int bp = blockIdx.x;
    int b = bp >> 12, p = bp & 4095;
    int h = p >> 6, w = p & 63;
    int hc = min(max(h,1),62), wc = min(max(w,1),62);

    __shared__ float sA[36];
    int tid = threadIdx.x;
    if (tid < 36) {
        int g = tid / 9, t = tid % 9;
        float a  = attn_out[(((size_t)(b*4 + g))*4096 + p)*9 + t];
        int np   = (hc + t/3 - 1)*64 + (wc + t%3 - 1);
        float cs = colsums[(b<<12) + np];
        float val = a / (cs + 1e-8f);
        sA[tid] = val;
        acol_out[(((size_t)(b*4 + g))*4096 + p)*9 + t] = val;
    }
    __syncthreads();

    float acc = 0.0f;
    #pragma unroll
    for (int g = 0; g < 4; g++) {
        #pragma unroll
        for (int t = 0; t < 9; t++) {
            int nh = hc + t/3 - 1, nw = wc + t%3 - 1;
            int tin = (2*nh + (g>>1))*128 + 2*nw + (g&1);
            acc += sA[g*9 + t] * Vv[((size_t)(b*16384 + tin))*DIMX + tid];
        }
    }
    size_t idx = ((size_t)(b<<12) + p)*DIMX + tid;
    float nv = x_out[idx] + acc;
    x_out[idx] = nv;
    __nv_bfloat16 hi = __float2bfloat16(nv);
    ((uint16_t*)g_xor_)[idx] = __bfloat16_as_ushort(hi);
    ((uint16_t*)g_xor_)[(size_t)NTOK*DIMX + idx] =
        __bfloat16_as_ushort(__float2bfloat16(nv - __bfloat162float(hi)));
}

// ---------------- launcher ----------------
extern "C" void kernel_launch(void* const* d_in, const int* in_sizes, int n_in,
                              void* d_out, int out_size)
{
    (void)in_sizes; (void)n_in; (void)out_size;
    const float* x        = (const float*)d_in[0];
    const float* conv_w   = (const float*)d_in[1];
    const float* q_w      = (const float*)d_in[2];
    const float* k_w      = (const float*)d_in[3];
    const float* v_w      = (const float*)d_in[4];
    const float* mlp_w1   = (const float*)d_in[5];
    const float* mlp_b1   = (const float*)d_in[6];
    const float* mlp_w2   = (const float*)d_in[7];
    const float* mlp_b2   = (const float*)d_in[8];
    const float* ln_in_g  = (const float*)d_in[9];
    const float* ln_in_b  = (const float*)d_in[10];
    const float* ln_out_g = (const float*)d_in[11];
    const float* ln_out_b = (const float*)d_in[12];
    const float* tau      = (const float*)d_in[13];
    const float* rpb      = (const float*)d_in[14];

    float* xout     = (float*)d_out;
    float* attn_out = xout + (size_t)NTOK * DIMX;
    float* acol_out = attn_out + (size_t)BATCH * 4 * NP * 9;

    float *p_k, *p_v, *p_q, *p_seed, *p_h2, *p_cs;
    __nv_bfloat16 *p_wimg, *p_xr, *p_xl, *p_xor, *p_xol, *p_hb;
    int* p_rows;
    cudaGetSymbolAddress((void**)&p_k,   g_k);
    cudaGetSymbolAddress((void**)&p_v,   g_v);
    cudaGetSymbolAddress((void**)&p_q,   g_q);
    cudaGetSymbolAddress((void**)&p_seed,g_seed);
    cudaGetSymbolAddress((void**)&p_h2,  g_h2);
    cudaGetSymbolAddress((void**)&p_cs,  g_cs);
    cudaGetSymbolAddress((void**)&p_wimg,g_wimg);
    cudaGetSymbolAddress((void**)&p_xr,  g_xr);
    cudaGetSymbolAddress((void**)&p_xl,  g_xl);
    cudaGetSymbolAddress((void**)&p_xor, g_xor_);
    cudaGetSymbolAddress((void**)&p_xol, g_xol);
    cudaGetSymbolAddress((void**)&p_hb,  g_hb);
    cudaGetSymbolAddress((void**)&p_rows,g_rows);

    static int attr_set = 0;
    if (!attr_set) {
        cudaFuncSetAttribute(tgemm2, cudaFuncAttributeMaxDynamicSharedMemorySize, TG_SMEM);
        attr_set = 1;
    }

    const size_t APL_BIG = (size_t)NTOKIN*DIMX;
    const size_t APL_TOK = (size_t)NTOK*DIMX;
    const size_t APL_H   = (size_t)NTOK*2*DIMX;

    // prep
    prep_conv<<<(9*NTOK + 255)/256, 256>>>(conv_w);
    prep_img<<<dim3(64, 16), 256>>>(k_w, v_w, q_w, mlp_w1, mlp_w2);
    split_x<<<NTOKIN/8, 256>>>(x, ln_in_g, ln_in_b);
    // k = LN_in(x) @ k_w ; v = x @ v_w
    tgemm2<<<dim3(2, NTOKIN/64), 256, TG_SMEM>>>(NTOKIN, 128, 1, p_xl, APL_BIG, 0, p_wimg + 0*32768, p_k, 128, 0, 0, 0, 0);
    tgemm2<<<dim3(2, NTOKIN/64), 256, TG_SMEM>>>(NTOKIN, 128, 1, p_xr, APL_BIG, 0, p_wimg + 1*32768, p_v, 128, 0, 0, 0, 0);
    // conv: 9 row-gathered K-segments
    tgemm2<<<dim3(2, NTOK/64), 256, TG_SMEM>>>(NTOK, 128, 9, p_xr, APL_BIG, p_rows, p_wimg + 7*32768, p_seed, 128, 0, 0, 0, 0);
    // x_out = LN(seed); also emits LN(xout) split for q
    ln2_kernel<<<NTOK/8, 256>>>(p_seed, xout, ln_out_g, ln_out_b, 0);

    for (int it = 0; it < 3; it++) {
        // q = LN_out(xout) @ q_w
        tgemm2<<<dim3(2, NTOK/64), 256, TG_SMEM>>>(NTOK, 128, 1, p_xol, APL_TOK, 0, p_wimg + 2*32768, p_q, 128, 0, 0, 0, 0);
        cudaMemsetAsync(p_cs, 0, NTOK * sizeof(float));
        attn_kernel<<<NTOK, 128>>>(p_k, p_q, rpb, tau, attn_out, p_cs);
        upd_kernel<<<NTOK, 128>>>(attn_out, p_cs, p_v, acol_out, xout);
        // mlp1: h = gelu(xout @ w1 + b1), written pre-split
        tgemm2<<<dim3(4, NTOK/64), 256, TG_SMEM>>>(NTOK, 128, 1, p_xor, APL_TOK, 0, p_wimg + 3*32768, 0, 256, mlp_b1, 1, p_hb, APL_H);
        // mlp2: h2 = h @ w2 + b2 (2 K-segments)
        tgemm2<<<dim3(2, NTOK/64), 256, TG_SMEM>>>(NTOK, 256, 2, p_hb, APL_H, 0, p_wimg + 5*32768, p_h2, 128, mlp_b2, 0, 0, 0);
        // xout += LN(h2); emits LN(xout) split
        ln2_kernel<<<NTOK/8, 256>>>(p_h2, xout, ln_out_g, ln_out_b, 1);
    }
}

// round 14
// speedup vs baseline: 1.0458x; 1.0458x over previous
#include <cuda_runtime.h>
#include <cuda_bf16.h>
#include <math.h>
#include <stdint.h>

#define HOx 64
#define WOx 64
#define DIMX 128
#define BATCH 4
#define NP (HOx*WOx)            /* 4096  */
#define NTOK (BATCH*NP)         /* 16384 */
#define NTOKIN (BATCH*128*128)  /* 65536 */

// ---------------- scratch (static device globals; no runtime alloc) ----------------
__device__ float g_k [(size_t)NTOKIN*DIMX];
__device__ float g_v [(size_t)NTOKIN*DIMX];
__device__ float g_q  [(size_t)NTOK*DIMX];
__device__ float g_seed[(size_t)NTOK*DIMX];
__device__ float g_h2[(size_t)NTOK*DIMX];
__device__ float g_cs[NTOK];
__device__ float g_wc[9*DIMX*DIMX];
__device__ int   g_rows[9*NTOK];
// 16 weight images, each: 16384 bf16 hi + 16384 bf16 lo, row-major [n][k]
__device__ __nv_bfloat16 g_wimg[16*32768];
// pre-split activation images: hi plane then lo plane
__device__ __nv_bfloat16 g_xr  [2*(size_t)NTOKIN*DIMX];  // raw x
__device__ __nv_bfloat16 g_xl  [2*(size_t)NTOKIN*DIMX];  // LN_in(x)
__device__ __nv_bfloat16 g_xor_[2*(size_t)NTOK*DIMX];    // raw xout (post-upd)
__device__ __nv_bfloat16 g_xol [2*(size_t)NTOK*DIMX];    // LN_out(xout)
__device__ __nv_bfloat16 g_hb  [2*(size_t)NTOK*2*DIMX];  // gelu(h)

// ---------------- PTX helpers ----------------
__device__ __forceinline__ uint32_t smem_u32(const void* p) {
    uint32_t a;
    asm("{ .reg .u64 t; cvta.to.shared.u64 t, %1; cvt.u32.u64 %0, t; }" : "=r"(a) : "l"(p));
    return a;
}
__device__ __forceinline__ void ldsm4(uint32_t addr, uint32_t& r0, uint32_t& r1, uint32_t& r2, uint32_t& r3)
{
    asm volatile("ldmatrix.sync.aligned.m8n8.x4.shared.b16 {%0,%1,%2,%3}, [%4];"
                 : "=r"(r0), "=r"(r1), "=r"(r2), "=r"(r3) : "r"(addr));
}
__device__ __forceinline__ void mma16816(float* c, const uint32_t* a,
                                         uint32_t b0, uint32_t b1)
{
    asm volatile("mma.sync.aligned.m16n8k16.row.col.f32.bf16.bf16.f32 "
                 "{%0,%1,%2,%3}, {%4,%5,%6,%7}, {%8,%9}, {%0,%1,%2,%3};"
                 : "+f"(c[0]), "+f"(c[1]), "+f"(c[2]), "+f"(c[3])
                 : "r"(a[0]), "r"(a[1]), "r"(a[2]), "r"(a[3]), "r"(b0), "r"(b1));
}
__device__ __forceinline__ void cp16(uint32_t dst, const void* src)
{
    asm volatile("cp.async.ca.shared.global [%0], [%1], 16;" :: "r"(dst), "l"(src));
}
__device__ __forceinline__ void cp16z(uint32_t dst, const void* src, int sz)
{
    asm volatile("cp.async.ca.shared.global [%0], [%1], 16, %2;" :: "r"(dst), "l"(src), "r"(sz));
}
#define CP_COMMIT() asm volatile("cp.async.commit_group;" ::: "memory")
#define CP_WAIT0()  asm volatile("cp.async.wait_group 0;" ::: "memory")

__device__ __forceinline__ uint32_t packbf(float a, float b)
{
    __nv_bfloat16 x = __float2bfloat16(a), y = __float2bfloat16(b);
    return (uint32_t)__bfloat16_as_ushort(x) | ((uint32_t)__bfloat16_as_ushort(y) << 16);
}
__device__ __forceinline__ void split4(float4 v, uint2& hp, uint2& lp)
{
    __nv_bfloat16 h0 = __float2bfloat16(v.x), h1 = __float2bfloat16(v.y);
    __nv_bfloat16 h2 = __float2bfloat16(v.z), h3 = __float2bfloat16(v.w);
    hp.x = (uint32_t)__bfloat16_as_ushort(h0) | ((uint32_t)__bfloat16_as_ushort(h1) << 16);
    hp.y = (uint32_t)__bfloat16_as_ushort(h2) | ((uint32_t)__bfloat16_as_ushort(h3) << 16);
    lp.x = packbf(v.x - __bfloat162float(h0), v.y - __bfloat162float(h1));
    lp.y = packbf(v.z - __bfloat162float(h2), v.w - __bfloat162float(h3));
}

// ---------------- prep: conv weight transpose + conv row-gather table ----------------
__global__ void prep_conv(const float* __restrict__ conv_w)
{
    int i = blockIdx.x * blockDim.x + threadIdx.x;
    if (i < 9*DIMX*DIMX) {
        int kk = i / (DIMX*DIMX);
        int r  = i % (DIMX*DIMX);
        int c  = r / DIMX, dout = r % DIMX;
        int ky = kk / 3, kx = kk % 3;
        g_wc[i] = conv_w[((dout*DIMX + c)*3 + ky)*3 + kx];
    }
    if (i < 9*NTOK) {
        int kk = i / NTOK;
        int m  = i % NTOK;
        int b  = m >> 12, p = m & 4095;
        int ho = p >> 6, wo = p & 63;
        int ky = kk / 3, kx = kk % 3;
        int y = 2*ho - 1 + ky;
        int x = 2*wo - 1 + kx;
        g_rows[i] = (y >= 0 && y < 128 && x >= 0 && x < 128) ? (b*16384 + y*128 + x) : -1;
    }
}

// ---------------- prep: 16 pre-split B images, row-major [n][k] (W transposed) ----------------
__global__ void prep_img(const float* __restrict__ k_w, const float* __restrict__ v_w,
                         const float* __restrict__ q_w, const float* __restrict__ mlp_w1,
                         const float* __restrict__ mlp_w2)
{
    int e   = blockIdx.x * blockDim.x + threadIdx.x; // 0..16383
    int img = blockIdx.y;                            // 0..15
    int k = e >> 7, n = e & 127;

    const float* src; int ldn, k0, n0;
    if      (img == 0) { src = k_w;    ldn = 128; k0 = 0;   n0 = 0;   }
    else if (img == 1) { src = v_w;    ldn = 128; k0 = 0;   n0 = 0;   }
    else if (img == 2) { src = q_w;    ldn = 128; k0 = 0;   n0 = 0;   }
    else if (img == 3) { src = mlp_w1; ldn = 256; k0 = 0;   n0 = 0;   }
    else if (img == 4) { src = mlp_w1; ldn = 256; k0 = 0;   n0 = 128; }
    else if (img == 5) { src = mlp_w2; ldn = 128; k0 = 0;   n0 = 0;   }
    else if (img == 6) { src = mlp_w2; ldn = 128; k0 = 128; n0 = 0;   }
    else               { src = g_wc + (img - 7)*DIMX*DIMX; ldn = 128; k0 = 0; n0 = 0; }

    float w = src[(size_t)(k0 + k) * ldn + n0 + n];
    __nv_bfloat16 hi = __float2bfloat16(w);
    __nv_bfloat16 lo = __float2bfloat16(w - __bfloat162float(hi));
    __nv_bfloat16* dst = g_wimg + (size_t)img * 32768;
    dst[n*128 + k]         = hi;
    dst[16384 + n*128 + k] = lo;
}

// ---------------- split x: raw split + LN_in split (warp per row) ----------------
__global__ void split_x(const float* __restrict__ x,
                        const float* __restrict__ g, const float* __restrict__ b)
{
    int row  = (blockIdx.x * blockDim.x + threadIdx.x) >> 5;
    int lane = threadIdx.x & 31;
    float4 v = ((const float4*)(x + (size_t)row * DIMX))[lane];
    uint2 hp, lp;
    split4(v, hp, lp);
    size_t off = (size_t)row * DIMX + lane*4;
    *(uint2*)((uint16_t*)g_xr + off)                          = hp;
    *(uint2*)((uint16_t*)g_xr + (size_t)NTOKIN*DIMX + off)    = lp;
    float s  = v.x + v.y + v.z + v.w;
    float sq = v.x*v.x + v.y*v.y + v.z*v.z + v.w*v.w;
    #pragma unroll
    for (int o = 16; o > 0; o >>= 1) {
        s  += __shfl_xor_sync(0xffffffffu, s,  o);
        sq += __shfl_xor_sync(0xffffffffu, sq, o);
    }
    float mu  = s * (1.0f/DIMX);
    float var = sq * (1.0f/DIMX) - mu*mu;
    float rs  = rsqrtf(var + 1e-5f);
    float4 g4 = ((const float4*)g)[lane];
    float4 b4 = ((const float4*)b)[lane];
    float4 t;
    t.x = (v.x - mu)*rs*g4.x + b4.x;
    t.y = (v.y - mu)*rs*g4.y + b4.y;
    t.z = (v.z - mu)*rs*g4.z + b4.z;
    t.w = (v.w - mu)*rs*g4.w + b4.w;
    split4(t, hp, lp);
    *(uint2*)((uint16_t*)g_xl + off)                          = hp;
    *(uint2*)((uint16_t*)g_xl + (size_t)NTOKIN*DIMX + off)    = lp;
}

// ---------------- ln2: xout = LN(in) (mode 0) or xout += LN(in) (mode 1);
//                  then write LN_out(xout) split for next q-gemm ----------------
__global__ void ln2_kernel(const float* __restrict__ in, float* __restrict__ xout,
                           const float* __restrict__ g, const float* __restrict__ b,
                           int mode)
{
    int row  = (blockIdx.x * blockDim.x + threadIdx.x) >> 5;
    int lane = threadIdx.x & 31;
    float4 v = ((const float4*)(in + (size_t)row * DIMX))[lane];
    float s  = v.x + v.y + v.z + v.w;
    float sq = v.x*v.x + v.y*v.y + v.z*v.z + v.w*v.w;
    #pragma unroll
    for (int o = 16; o > 0; o >>= 1) {
        s  += __shfl_xor_sync(0xffffffffu, s,  o);
        sq += __shfl_xor_sync(0xffffffffu, sq, o);
    }
    float mu  = s * (1.0f/DIMX);
    float var = sq * (1.0f/DIMX) - mu*mu;
    float rs  = rsqrtf(var + 1e-5f);
    float4 g4 = ((const float4*)g)[lane];
    float4 b4 = ((const float4*)b)[lane];
    float4 t;
    t.x = (v.x - mu)*rs*g4.x + b4.x;
    t.y = (v.y - mu)*rs*g4.y + b4.y;
    t.z = (v.z - mu)*rs*g4.z + b4.z;
    t.w = (v.w - mu)*rs*g4.w + b4.w;
    float4* op = (float4*)(xout + (size_t)row * DIMX);
    if (mode) {
        float4 e = op[lane];
        t.x += e.x; t.y += e.y; t.z += e.z; t.w += e.w;
    }
    op[lane] = t;
    // second LN on the new xout row
    s  = t.x + t.y + t.z + t.w;
    sq = t.x*t.x + t.y*t.y + t.z*t.z + t.w*t.w;
    #pragma unroll
    for (int o = 16; o > 0; o >>= 1) {
        s  += __shfl_xor_sync(0xffffffffu, s,  o);
        sq += __shfl_xor_sync(0xffffffffu, sq, o);
    }
    mu  = s * (1.0f/DIMX);
    var = sq * (1.0f/DIMX) - mu*mu;
    rs  = rsqrtf(var + 1e-5f);
    float4 u;
    u.x = (t.x - mu)*rs*g4.x + b4.x;
    u.y = (t.y - mu)*rs*g4.y + b4.y;
    u.z = (t.z - mu)*rs*g4.z + b4.z;
    u.w = (t.w - mu)*rs*g4.w + b4.w;
    uint2 hp, lp;
    split4(u, hp, lp);
    size_t off = (size_t)row * DIMX + lane*4;
    *(uint2*)((uint16_t*)g_xol + off)                        = hp;
    *(uint2*)((uint16_t*)g_xol + (size_t)NTOK*DIMX + off)    = lp;
}

__device__ __forceinline__ float gelu_exact(float x)
{
    return 0.5f * x * (1.0f + erff(x * 0.70710678118654752f));
}

// ---------------- tensor-core GEMM: BM64xBN128, 2 CTAs/SM, multi-tile B reuse ----------------
// mtiles: consecutive 64-row tiles per CTA sharing one smem-resident B (nseg must be 1 if >1).
#define TSTRIDE 136
#define TILE_A (64*TSTRIDE*2)      /* 17408 bytes */
#define TILE_B (128*TSTRIDE*2)     /* 34816 bytes */
#define TG_SMEM (2*TILE_A + 2*TILE_B)  /* 104448 */

__global__ __launch_bounds__(256, 2)
void tgemm2(int M, int Krow, int nseg, int mtiles,
            const __nv_bfloat16* __restrict__ Aimg, size_t Aplane,
            const int* __restrict__ rowtab,
            const __nv_bfloat16* __restrict__ Bimg,
            float* __restrict__ C, int ldc,
            const float* __restrict__ bias, int act,
            __nv_bfloat16* OutSplit, size_t Oplane)
{
    extern __shared__ char smem[];
    const uint32_t sb = smem_u32(smem);
    const uint32_t A_HI = sb, A_LO = sb + TILE_A, B_HI = sb + 2*TILE_A, B_LO = sb + 2*TILE_A + TILE_B;

    const int tid = threadIdx.x, wid = tid >> 5, lane = tid & 31;
    const int bcol = blockIdx.x * 128;
    const int rowbase = (wid & 1) * 32;
    const int colbase = (wid >> 1) * 32;

    const uint32_t aAddr0 = (uint32_t)((rowbase + (lane & 15)) * (TSTRIDE*2) + (lane >> 4) * 16);
    const uint32_t bAddr0 = (uint32_t)((colbase + (lane & 7))  * (TSTRIDE*2) + (lane >> 3) * 16);

    for (int t = 0; t < mtiles; t++) {
        const int brow = (blockIdx.y * mtiles + t) * 64;

        float acc[2][4][4];
        #pragma unroll
        for (int mt = 0; mt < 2; mt++)
            #pragma unroll
            for (int nt = 0; nt < 4; nt++)
                #pragma unroll
                for (int r = 0; r < 4; r++) acc[mt][nt][r] = 0.0f;

        for (int seg = 0; seg < nseg; seg++) {
            if (t || seg) __syncthreads();

            // ---- A tile: 2048 16B chunks (hi+lo), cp.async with zero-fill for OOB rows ----
            {
                const int acol = rowtab ? 0 : seg * 128;
                #pragma unroll
                for (int i = 0; i < 8; i++) {
                    int idx   = i * 256 + tid;          // 0..2047
                    int plane = idx >> 10;              // 0 hi, 1 lo
                    int r     = (idx >> 4) & 63;
                    int ch    = idx & 15;
                    int srow  = rowtab ? rowtab[(size_t)seg * M + brow + r] : (brow + r);
                    uint32_t dst = (plane ? A_LO : A_HI) + (uint32_t)(r * (TSTRIDE*2) + ch * 16);
                    const __nv_bfloat16* src = Aimg + (size_t)plane * Aplane
                                             + (size_t)(srow < 0 ? 0 : srow) * Krow + acol + ch * 8;
                    cp16z(dst, src, srow < 0 ? 0 : 16);
                }
            }
            // ---- B tile: 4096 16B chunks (only first tile; stays resident after) ----
            if (t == 0) {
                const __nv_bfloat16* Bseg = Bimg + ((size_t)(blockIdx.x * nseg + seg)) * 32768;
                #pragma unroll
                for (int i = 0; i < 16; i++) {
                    int idx   = i * 256 + tid;          // 0..4095
                    int plane = idx >> 11;
                    int r     = (idx >> 4) & 127;
                    int ch    = idx & 15;
                    uint32_t dst = (plane ? B_LO : B_HI) + (uint32_t)(r * (TSTRIDE*2) + ch * 16);
                    cp16(dst, Bseg + plane * 16384 + r * 128 + ch * 8);
                }
            }
            CP_COMMIT();
            CP_WAIT0();
            __syncthreads();

            // ---- cached fragments; 3 passes from registers ----
            #pragma unroll
            for (int kc = 0; kc < 4; kc++) {
                uint32_t bh[4][4], bl[4][4];
                #pragma unroll
                for (int nt = 0; nt < 4; nt++) {
                    uint32_t boff = bAddr0 + nt*8*(TSTRIDE*2) + kc*64;
                    ldsm4(B_HI + boff, bh[nt][0], bh[nt][1], bh[nt][2], bh[nt][3]);
                    ldsm4(B_LO + boff, bl[nt][0], bl[nt][1], bl[nt][2], bl[nt][3]);
                }
                uint32_t ah[2][2][4], al[2][2][4];
                #pragma unroll
                for (int half = 0; half < 2; half++)
                    #pragma unroll
                    for (int mt = 0; mt < 2; mt++) {
                        uint32_t aoff = aAddr0 + mt*16*(TSTRIDE*2) + kc*64 + half*32;
                        ldsm4(A_HI + aoff, ah[half][mt][0], ah[half][mt][1], ah[half][mt][2], ah[half][mt][3]);
                        ldsm4(A_LO + aoff, al[half][mt][0], al[half][mt][1], al[half][mt][2], al[half][mt][3]);
                    }
                #pragma unroll
                for (int half = 0; half < 2; half++)
                    #pragma unroll
                    for (int mt = 0; mt < 2; mt++)
                        #pragma unroll
                        for (int nt = 0; nt < 4; nt++)
                            mma16816(acc[mt][nt], ah[half][mt], bh[nt][half*2], bh[nt][half*2+1]);
                #pragma unroll
                for (int half = 0; half < 2; half++)
                    #pragma unroll
                    for (int mt = 0; mt < 2; mt++)
                        #pragma unroll
                        for (int nt = 0; nt < 4; nt++)
                            mma16816(acc[mt][nt], ah[half][mt], bl[nt][half*2], bl[nt][half*2+1]);
                #pragma unroll
                for (int half = 0; half < 2; half++)
                    #pragma unroll
                    for (int mt = 0; mt < 2; mt++)
                        #pragma unroll
                        for (int nt = 0; nt < 4; nt++)
                            mma16816(acc[mt][nt], al[half][mt], bh[nt][half*2], bh[nt][half*2+1]);
            }
        }

        // ---- epilogue for this tile ----
        #pragma unroll
        for (int mt = 0; mt < 2; mt++) {
            int r0 = brow + rowbase + mt*16 + (lane >> 2);
            #pragma unroll
            for (int nt = 0; nt < 4; nt++) {
                int c = bcol + colbase + nt*8 + (lane & 3)*2;
                float v0 = acc[mt][nt][0], v1 = acc[mt][nt][1];
                float v2 = acc[mt][nt][2], v3 = acc[mt][nt][3];
                if (bias) {
                    float b0 = bias[c], b1 = bias[c+1];
                    v0 += b0; v1 += b1; v2 += b0; v3 += b1;
                }
                if (act) {
                    v0 = gelu_exact(v0); v1 = gelu_exact(v1);
                    v2 = gelu_exact(v2); v3 = gelu_exact(v3);
                }
                if (OutSplit) {
                    uint16_t* hi = (uint16_t*)OutSplit;
                    uint16_t* lo = hi + Oplane;
                    __nv_bfloat16 h0 = __float2bfloat16(v0), h1 = __float2bfloat16(v1);
                    __nv_bfloat16 h2 = __float2bfloat16(v2), h3 = __float2bfloat16(v3);
                    *(uint32_t*)(hi + (size_t)r0*ldc + c) =
                        (uint32_t)__bfloat16_as_ushort(h0) | ((uint32_t)__bfloat16_as_ushort(h1) << 16);
                    *(uint32_t*)(lo + (size_t)r0*ldc + c) =
                        packbf(v0 - __bfloat162float(h0), v1 - __bfloat162float(h1));
                    *(uint32_t*)(hi + (size_t)(r0+8)*ldc + c) =
                        (uint32_t)__bfloat16_as_ushort(h2) | ((uint32_t)__bfloat16_as_ushort(h3) << 16);
                    *(uint32_t*)(lo + (size_t)(r0+8)*ldc + c) =
                        packbf(v2 - __bfloat162float(h2), v3 - __bfloat162float(h3));
                } else {
                    *(float2*)(C + (size_t)r0 * ldc + c)     = make_float2(v0, v1);
                    *(float2*)(C + (size_t)(r0+8) * ldc + c) = make_float2(v2, v3);
                }
            }
        }
    }
}

// ---------------- attention: dots + softmax + eps, atomic col sums ----------------
__global__ __launch_bounds__(128)
void attn_kernel(const float* __restrict__ Kv, const float* __restrict__ Qv,
                 const float* __restrict__ rpb, const float* __restrict__ tau,
                 float* __restrict__ attn_out, float* __restrict__ colsums)
{
    int bp = blockIdx.x;
    int b = bp >> 12, p = bp & 4095;
    int h = p >> 6, w = p & 63;
    int hc = min(max(h,1),62), wc = min(max(w,1),62);

    __shared__ __align__(16) float q_sh[9][128];
    int tid = threadIdx.x;
    #pragma unroll
    for (int t = 0; t < 9; t++) {
        int np = (hc + t/3 - 1)*64 + (wc + t%3 - 1);
        q_sh[t][tid] = Qv[((size_t)(b<<12) + np)*DIMX + tid];
    }
    __syncthreads();

    int g = tid >> 5, lane = tid & 31;
    int tin = (2*h + (g>>1))*128 + 2*w + (g&1);
    float4 kv = *(const float4*)(Kv + ((size_t)(b*16384 + tin))*DIMX + lane*4);

    float myd = 0.0f;
    #pragma unroll
    for (int t = 0; t < 9; t++) {
        float4 qv = *(const float4*)(&q_sh[t][lane*4]);
        float d = kv.x*qv.x + kv.y*qv.y + kv.z*qv.z + kv.w*qv.w;
        #pragma unroll
        for (int o = 16; o > 0; o >>= 1) d += __shfl_xor_sync(0xffffffffu, d, o);
        if (lane == t) myd = d;
    }

    float scale = expf(*tau);
    float z = (lane < 9) ? (myd + rpb[g*9 + lane]) * scale : -1e30f;
    float m = z;
    #pragma unroll
    for (int o = 16; o > 0; o >>= 1) m = fmaxf(m, __shfl_xor_sync(0xffffffffu, m, o));
    float e = (lane < 9) ? expf(z - m) : 0.0f;
    float s = e;
    #pragma unroll
    for (int o = 16; o > 0; o >>= 1) s += __shfl_xor_sync(0xffffffffu, s, o);

    if (lane < 9) {
        float a = e / s + 1e-6f;
        attn_out[(((size_t)(b*4 + g))*4096 + p)*9 + lane] = a;
        int np = (hc + lane/3 - 1)*64 + (wc + lane%3 - 1);
        atomicAdd(&colsums[(b<<12) + np], a);
    }
}

// ---------------- column-normalize + weighted v gather; x_out += upd; raw split out ----
__global__ __launch_bounds__(128)
void upd_kernel(const float* __restrict__ attn_out, const float* __restrict__ colsums,
                const float* __restrict__ Vv, float* __restrict__ acol_out,
                float* __restrict__ x_out)
{
    int bp = blockIdx.x;
    int b = bp >> 12, p = bp & 4095;
    int h = p >> 6, w = p & 63;
    int hc = min(max(h,1),62), wc = min(max(w,1),62);

    __shared__ float sA[36];
    int tid = threadIdx.x;
    if (tid < 36) {
        int g = tid / 9, t = tid % 9;
        float a  = attn_out[(((size_t)(b*4 + g))*4096 + p)*9 + t];
        int np   = (hc + t/3 - 1)*64 + (wc + t%3 - 1);
        float cs = colsums[(b<<12) + np];
        float val = a / (cs + 1e-8f);
        sA[tid] = val;
        acol_out[(((size_t)(b*4 + g))*4096 + p)*9 + t] = val;
    }
    __syncthreads();

    float acc = 0.0f;
    #pragma unroll
    for (int g = 0; g < 4; g++) {
        #pragma unroll
        for (int t = 0; t < 9; t++) {
            int nh = hc + t/3 - 1, nw = wc + t%3 - 1;
            int tin = (2*nh + (g>>1))*128 + 2*nw + (g&1);
            acc += sA[g*9 + t] * Vv[((size_t)(b*16384 + tin))*DIMX + tid];
        }
    }
    size_t idx = ((size_t)(b<<12) + p)*DIMX + tid;
    float nv = x_out[idx] + acc;
    x_out[idx] = nv;
    __nv_bfloat16 hi = __float2bfloat16(nv);
    ((uint16_t*)g_xor_)[idx] = __bfloat16_as_ushort(hi);
    ((uint16_t*)g_xor_)[(size_t)NTOK*DIMX + idx] =
        __bfloat16_as_ushort(__float2bfloat16(nv - __bfloat162float(hi)));
}

// ---------------- launcher ----------------
extern "C" void kernel_launch(void* const* d_in, const int* in_sizes, int n_in,
                              void* d_out, int out_size)
{
    (void)in_sizes; (void)n_in; (void)out_size;
    const float* x        = (const float*)d_in[0];
    const float* conv_w   = (const float*)d_in[1];
    const float* q_w      = (const float*)d_in[2];
    const float* k_w      = (const float*)d_in[3];
    const float* v_w      = (const float*)d_in[4];
    const float* mlp_w1   = (const float*)d_in[5];
    const float* mlp_b1   = (const float*)d_in[6];
    const float* mlp_w2   = (const float*)d_in[7];
    const float* mlp_b2   = (const float*)d_in[8];
    const float* ln_in_g  = (const float*)d_in[9];
    const float* ln_in_b  = (const float*)d_in[10];
    const float* ln_out_g = (const float*)d_in[11];
    const float* ln_out_b = (const float*)d_in[12];
    const float* tau      = (const float*)d_in[13];
    const float* rpb      = (const float*)d_in[14];

    float* xout     = (float*)d_out;
    float* attn_out = xout + (size_t)NTOK * DIMX;
    float* acol_out = attn_out + (size_t)BATCH * 4 * NP * 9;

    float *p_k, *p_v, *p_q, *p_seed, *p_h2, *p_cs;
    __nv_bfloat16 *p_wimg, *p_xr, *p_xl, *p_xor, *p_xol, *p_hb;
    int* p_rows;
    cudaGetSymbolAddress((void**)&p_k,   g_k);
    cudaGetSymbolAddress((void**)&p_v,   g_v);
    cudaGetSymbolAddress((void**)&p_q,   g_q);
    cudaGetSymbolAddress((void**)&p_seed,g_seed);
    cudaGetSymbolAddress((void**)&p_h2,  g_h2);
    cudaGetSymbolAddress((void**)&p_cs,  g_cs);
    cudaGetSymbolAddress((void**)&p_wimg,g_wimg);
    cudaGetSymbolAddress((void**)&p_xr,  g_xr);
    cudaGetSymbolAddress((void**)&p_xl,  g_xl);
    cudaGetSymbolAddress((void**)&p_xor, g_xor_);
    cudaGetSymbolAddress((void**)&p_xol, g_xol);
    cudaGetSymbolAddress((void**)&p_hb,  g_hb);
    cudaGetSymbolAddress((void**)&p_rows,g_rows);

    static int attr_set = 0;
    if (!attr_set) {
        cudaFuncSetAttribute(tgemm2, cudaFuncAttributeMaxDynamicSharedMemorySize, TG_SMEM);
        attr_set = 1;
    }

    const size_t APL_BIG = (size_t)NTOKIN*DIMX;
    const size_t APL_TOK = (size_t)NTOK*DIMX;
    const size_t APL_H   = (size_t)NTOK*2*DIMX;

    // prep
    prep_conv<<<(9*NTOK + 255)/256, 256>>>(conv_w);
    prep_img<<<dim3(64, 16), 256>>>(k_w, v_w, q_w, mlp_w1, mlp_w2);
    split_x<<<NTOKIN/8, 256>>>(x, ln_in_g, ln_in_b);
    // k = LN_in(x) @ k_w ; v = x @ v_w  (mtiles=2: B stays resident across 2 tiles)
    tgemm2<<<dim3(1, NTOKIN/128), 256, TG_SMEM>>>(NTOKIN, 128, 1, 2, p_xl, APL_BIG, 0, p_wimg + 0*32768, p_k, 128, 0, 0, 0, 0);
    tgemm2<<<dim3(1, NTOKIN/128), 256, TG_SMEM>>>(NTOKIN, 128, 1, 2, p_xr, APL_BIG, 0, p_wimg + 1*32768, p_v, 128, 0, 0, 0, 0);
    // conv: 9 row-gathered K-segments (mtiles=1)
    tgemm2<<<dim3(1, NTOK/64), 256, TG_SMEM>>>(NTOK, 128, 9, 1, p_xr, APL_BIG, p_rows, p_wimg + 7*32768, p_seed, 128, 0, 0, 0, 0);
    // x_out = LN(seed); also emits LN(xout) split for q
    ln2_kernel<<<NTOK/8, 256>>>(p_seed, xout, ln_out_g, ln_out_b, 0);

    for (int it = 0; it < 3; it++) {
        // q = LN_out(xout) @ q_w (mtiles=1: keep 256-CTA grid fill)
        tgemm2<<<dim3(1, NTOK/64), 256, TG_SMEM>>>(NTOK, 128, 1, 1, p_xol, APL_TOK, 0, p_wimg + 2*32768, p_q, 128, 0, 0, 0, 0);
        cudaMemsetAsync(p_cs, 0, NTOK * sizeof(float));
        attn_kernel<<<NTOK, 128>>>(p_k, p_q, rpb, tau, attn_out, p_cs);
        upd_kernel<<<NTOK, 128>>>(attn_out, p_cs, p_v, acol_out, xout);
        // mlp1: h = gelu(xout @ w1 + b1), pre-split output (mtiles=2 -> 256 CTAs)
        tgemm2<<<dim3(2, NTOK/128), 256, TG_SMEM>>>(NTOK, 128, 1, 2, p_xor, APL_TOK, 0, p_wimg + 3*32768, 0, 256, mlp_b1, 1, p_hb, APL_H);
        // mlp2: h2 = h @ w2 + b2 (2 K-segments, mtiles=1)
        tgemm2<<<dim3(1, NTOK/64), 256, TG_SMEM>>>(NTOK, 256, 2, 1, p_hb, APL_H, 0, p_wimg + 5*32768, p_h2, 128, mlp_b2, 0, 0, 0);
        // xout += LN(h2); emits LN(xout) split
        ln2_kernel<<<NTOK/8, 256>>>(p_h2, xout, ln_out_g, ln_out_b, 1);
    }
}

// round 15
// speedup vs baseline: 1.0688x; 1.0220x over previous
#include <cuda_runtime.h>
#include <cuda_bf16.h>
#include <math.h>
#include <stdint.h>

#define HOx 64
#define WOx 64
#define DIMX 128
#define BATCH 4
#define NP (HOx*WOx)            /* 4096  */
#define NTOK (BATCH*NP)         /* 16384 */
#define NTOKIN (BATCH*128*128)  /* 65536 */

// ---------------- scratch (static device globals; no runtime alloc) ----------------
__device__ float g_k [(size_t)NTOKIN*DIMX];
__device__ float g_v [(size_t)NTOKIN*DIMX];
__device__ float g_q  [(size_t)NTOK*DIMX];
__device__ float g_seed[(size_t)NTOK*DIMX];
__device__ float g_h2[(size_t)NTOK*DIMX];
__device__ float g_cs[NTOK];
__device__ float g_wc[9*DIMX*DIMX];
__device__ int   g_rows[9*NTOK];
// 16 weight images, each: 16384 bf16 hi + 16384 bf16 lo, row-major [n][k]
__device__ __nv_bfloat16 g_wimg[16*32768];
// pre-split activation images: hi plane then lo plane
__device__ __nv_bfloat16 g_xr  [2*(size_t)NTOKIN*DIMX];  // raw x
__device__ __nv_bfloat16 g_xl  [2*(size_t)NTOKIN*DIMX];  // LN_in(x)
__device__ __nv_bfloat16 g_xor_[2*(size_t)NTOK*DIMX];    // raw xout (post-upd)
__device__ __nv_bfloat16 g_xol [2*(size_t)NTOK*DIMX];    // LN_out(xout)
__device__ __nv_bfloat16 g_hb  [2*(size_t)NTOK*2*DIMX];  // gelu(h)

// ---------------- PTX helpers ----------------
__device__ __forceinline__ uint32_t smem_u32(const void* p) {
    uint32_t a;
    asm("{ .reg .u64 t; cvta.to.shared.u64 t, %1; cvt.u32.u64 %0, t; }" : "=r"(a) : "l"(p));
    return a;
}
__device__ __forceinline__ void ldsm4(uint32_t addr, uint32_t& r0, uint32_t& r1, uint32_t& r2, uint32_t& r3)
{
    asm volatile("ldmatrix.sync.aligned.m8n8.x4.shared.b16 {%0,%1,%2,%3}, [%4];"
                 : "=r"(r0), "=r"(r1), "=r"(r2), "=r"(r3) : "r"(addr));
}
__device__ __forceinline__ void mma16816(float* c, const uint32_t* a,
                                         uint32_t b0, uint32_t b1)
{
    asm volatile("mma.sync.aligned.m16n8k16.row.col.f32.bf16.bf16.f32 "
                 "{%0,%1,%2,%3}, {%4,%5,%6,%7}, {%8,%9}, {%0,%1,%2,%3};"
                 : "+f"(c[0]), "+f"(c[1]), "+f"(c[2]), "+f"(c[3])
                 : "r"(a[0]), "r"(a[1]), "r"(a[2]), "r"(a[3]), "r"(b0), "r"(b1));
}
__device__ __forceinline__ void cp16(uint32_t dst, const void* src)
{
    asm volatile("cp.async.ca.shared.global [%0], [%1], 16;" :: "r"(dst), "l"(src));
}
__device__ __forceinline__ void cp16z(uint32_t dst, const void* src, int sz)
{
    asm volatile("cp.async.ca.shared.global [%0], [%1], 16, %2;" :: "r"(dst), "l"(src), "r"(sz));
}
#define CP_COMMIT() asm volatile("cp.async.commit_group;" ::: "memory")
#define CP_WAIT0()  asm volatile("cp.async.wait_group 0;" ::: "memory")

__device__ __forceinline__ uint32_t packbf(float a, float b)
{
    __nv_bfloat16 x = __float2bfloat16(a), y = __float2bfloat16(b);
    return (uint32_t)__bfloat16_as_ushort(x) | ((uint32_t)__bfloat16_as_ushort(y) << 16);
}
__device__ __forceinline__ void split4(float4 v, uint2& hp, uint2& lp)
{
    __nv_bfloat16 h0 = __float2bfloat16(v.x), h1 = __float2bfloat16(v.y);
    __nv_bfloat16 h2 = __float2bfloat16(v.z), h3 = __float2bfloat16(v.w);
    hp.x = (uint32_t)__bfloat16_as_ushort(h0) | ((uint32_t)__bfloat16_as_ushort(h1) << 16);
    hp.y = (uint32_t)__bfloat16_as_ushort(h2) | ((uint32_t)__bfloat16_as_ushort(h3) << 16);
    lp.x = packbf(v.x - __bfloat162float(h0), v.y - __bfloat162float(h1));
    lp.y = packbf(v.z - __bfloat162float(h2), v.w - __bfloat162float(h3));
}

// ---------------- prep: conv weight transpose + conv row-gather table ----------------
__global__ void prep_conv(const float* __restrict__ conv_w)
{
    int i = blockIdx.x * blockDim.x + threadIdx.x;
    if (i < 9*DIMX*DIMX) {
        int kk = i / (DIMX*DIMX);
        int r  = i % (DIMX*DIMX);
        int c  = r / DIMX, dout = r % DIMX;
        int ky = kk / 3, kx = kk % 3;
        g_wc[i] = conv_w[((dout*DIMX + c)*3 + ky)*3 + kx];
    }
    if (i < 9*NTOK) {
        int kk = i / NTOK;
        int m  = i % NTOK;
        int b  = m >> 12, p = m & 4095;
        int ho = p >> 6, wo = p & 63;
        int ky = kk / 3, kx = kk % 3;
        int y = 2*ho - 1 + ky;
        int x = 2*wo - 1 + kx;
        g_rows[i] = (y >= 0 && y < 128 && x >= 0 && x < 128) ? (b*16384 + y*128 + x) : -1;
    }
}

// ---------------- prep: 16 pre-split B images, row-major [n][k] (W transposed) ----------------
__global__ void prep_img(const float* __restrict__ k_w, const float* __restrict__ v_w,
                         const float* __restrict__ q_w, const float* __restrict__ mlp_w1,
                         const float* __restrict__ mlp_w2)
{
    int e   = blockIdx.x * blockDim.x + threadIdx.x; // 0..16383
    int img = blockIdx.y;                            // 0..15
    int k = e >> 7, n = e & 127;

    const float* src; int ldn, k0, n0;
    if      (img == 0) { src = k_w;    ldn = 128; k0 = 0;   n0 = 0;   }
    else if (img == 1) { src = v_w;    ldn = 128; k0 = 0;   n0 = 0;   }
    else if (img == 2) { src = q_w;    ldn = 128; k0 = 0;   n0 = 0;   }
    else if (img == 3) { src = mlp_w1; ldn = 256; k0 = 0;   n0 = 0;   }
    else if (img == 4) { src = mlp_w1; ldn = 256; k0 = 0;   n0 = 128; }
    else if (img == 5) { src = mlp_w2; ldn = 128; k0 = 0;   n0 = 0;   }
    else if (img == 6) { src = mlp_w2; ldn = 128; k0 = 128; n0 = 0;   }
    else               { src = g_wc + (img - 7)*DIMX*DIMX; ldn = 128; k0 = 0; n0 = 0; }

    float w = src[(size_t)(k0 + k) * ldn + n0 + n];
    __nv_bfloat16 hi = __float2bfloat16(w);
    __nv_bfloat16 lo = __float2bfloat16(w - __bfloat162float(hi));
    __nv_bfloat16* dst = g_wimg + (size_t)img * 32768;
    dst[n*128 + k]         = hi;
    dst[16384 + n*128 + k] = lo;
}

// ---------------- split x: raw split + LN_in split (warp per row) ----------------
__global__ void split_x(const float* __restrict__ x,
                        const float* __restrict__ g, const float* __restrict__ b)
{
    int row  = (blockIdx.x * blockDim.x + threadIdx.x) >> 5;
    int lane = threadIdx.x & 31;
    float4 v = ((const float4*)(x + (size_t)row * DIMX))[lane];
    uint2 hp, lp;
    split4(v, hp, lp);
    size_t off = (size_t)row * DIMX + lane*4;
    *(uint2*)((uint16_t*)g_xr + off)                          = hp;
    *(uint2*)((uint16_t*)g_xr + (size_t)NTOKIN*DIMX + off)    = lp;
    float s  = v.x + v.y + v.z + v.w;
    float sq = v.x*v.x + v.y*v.y + v.z*v.z + v.w*v.w;
    #pragma unroll
    for (int o = 16; o > 0; o >>= 1) {
        s  += __shfl_xor_sync(0xffffffffu, s,  o);
        sq += __shfl_xor_sync(0xffffffffu, sq, o);
    }
    float mu  = s * (1.0f/DIMX);
    float var = sq * (1.0f/DIMX) - mu*mu;
    float rs  = rsqrtf(var + 1e-5f);
    float4 g4 = ((const float4*)g)[lane];
    float4 b4 = ((const float4*)b)[lane];
    float4 t;
    t.x = (v.x - mu)*rs*g4.x + b4.x;
    t.y = (v.y - mu)*rs*g4.y + b4.y;
    t.z = (v.z - mu)*rs*g4.z + b4.z;
    t.w = (v.w - mu)*rs*g4.w + b4.w;
    split4(t, hp, lp);
    *(uint2*)((uint16_t*)g_xl + off)                          = hp;
    *(uint2*)((uint16_t*)g_xl + (size_t)NTOKIN*DIMX + off)    = lp;
}

// ---------------- ln2: xout = LN(in) (mode 0) or xout += LN(in) (mode 1);
//                  then write LN_out(xout) split for next q-gemm ----------------
__global__ void ln2_kernel(const float* __restrict__ in, float* __restrict__ xout,
                           const float* __restrict__ g, const float* __restrict__ b,
                           int mode)
{
    int row  = (blockIdx.x * blockDim.x + threadIdx.x) >> 5;
    int lane = threadIdx.x & 31;
    float4 v = ((const float4*)(in + (size_t)row * DIMX))[lane];
    float s  = v.x + v.y + v.z + v.w;
    float sq = v.x*v.x + v.y*v.y + v.z*v.z + v.w*v.w;
    #pragma unroll
    for (int o = 16; o > 0; o >>= 1) {
        s  += __shfl_xor_sync(0xffffffffu, s,  o);
        sq += __shfl_xor_sync(0xffffffffu, sq, o);
    }
    float mu  = s * (1.0f/DIMX);
    float var = sq * (1.0f/DIMX) - mu*mu;
    float rs  = rsqrtf(var + 1e-5f);
    float4 g4 = ((const float4*)g)[lane];
    float4 b4 = ((const float4*)b)[lane];
    float4 t;
    t.x = (v.x - mu)*rs*g4.x + b4.x;
    t.y = (v.y - mu)*rs*g4.y + b4.y;
    t.z = (v.z - mu)*rs*g4.z + b4.z;
    t.w = (v.w - mu)*rs*g4.w + b4.w;
    float4* op = (float4*)(xout + (size_t)row * DIMX);
    if (mode) {
        float4 e = op[lane];
        t.x += e.x; t.y += e.y; t.z += e.z; t.w += e.w;
    }
    op[lane] = t;
    // second LN on the new xout row
    s  = t.x + t.y + t.z + t.w;
    sq = t.x*t.x + t.y*t.y + t.z*t.z + t.w*t.w;
    #pragma unroll
    for (int o = 16; o > 0; o >>= 1) {
        s  += __shfl_xor_sync(0xffffffffu, s,  o);
        sq += __shfl_xor_sync(0xffffffffu, sq, o);
    }
    mu  = s * (1.0f/DIMX);
    var = sq * (1.0f/DIMX) - mu*mu;
    rs  = rsqrtf(var + 1e-5f);
    float4 u;
    u.x = (t.x - mu)*rs*g4.x + b4.x;
    u.y = (t.y - mu)*rs*g4.y + b4.y;
    u.z = (t.z - mu)*rs*g4.z + b4.z;
    u.w = (t.w - mu)*rs*g4.w + b4.w;
    uint2 hp, lp;
    split4(u, hp, lp);
    size_t off = (size_t)row * DIMX + lane*4;
    *(uint2*)((uint16_t*)g_xol + off)                        = hp;
    *(uint2*)((uint16_t*)g_xol + (size_t)NTOK*DIMX + off)    = lp;
}

__device__ __forceinline__ float gelu_exact(float x)
{
    return 0.5f * x * (1.0f + erff(x * 0.70710678118654752f));
}

// ---------------- tensor-core GEMM body: BM64xBN128, multi-tile B reuse ----------------
#define TSTRIDE 136
#define TILE_A (64*TSTRIDE*2)      /* 17408 bytes */
#define TILE_B (128*TSTRIDE*2)     /* 34816 bytes */
#define TG_SMEM (2*TILE_A + 2*TILE_B)  /* 104448 */

__device__ __forceinline__
void tgemm_body(char* smem, int bx, int by,
                int M, int Krow, int nseg, int mtiles,
                const __nv_bfloat16* __restrict__ Aimg, size_t Aplane,
                const int* __restrict__ rowtab,
                const __nv_bfloat16* __restrict__ Bimg,
                float* __restrict__ C, int ldc,
                const float* __restrict__ bias, int act,
                __nv_bfloat16* OutSplit, size_t Oplane)
{
    const uint32_t sb = smem_u32(smem);
    const uint32_t A_HI = sb, A_LO = sb + TILE_A, B_HI = sb + 2*TILE_A, B_LO = sb + 2*TILE_A + TILE_B;

    const int tid = threadIdx.x, wid = tid >> 5, lane = tid & 31;
    const int bcol = bx * 128;
    const int rowbase = (wid & 1) * 32;
    const int colbase = (wid >> 1) * 32;

    const uint32_t aAddr0 = (uint32_t)((rowbase + (lane & 15)) * (TSTRIDE*2) + (lane >> 4) * 16);
    const uint32_t bAddr0 = (uint32_t)((colbase + (lane & 7))  * (TSTRIDE*2) + (lane >> 3) * 16);

    for (int t = 0; t < mtiles; t++) {
        const int brow = (by * mtiles + t) * 64;

        float acc[2][4][4];
        #pragma unroll
        for (int mt = 0; mt < 2; mt++)
            #pragma unroll
            for (int nt = 0; nt < 4; nt++)
                #pragma unroll
                for (int r = 0; r < 4; r++) acc[mt][nt][r] = 0.0f;

        for (int seg = 0; seg < nseg; seg++) {
            if (t || seg) __syncthreads();

            // ---- A tile: 2048 16B chunks (hi+lo), cp.async with zero-fill for OOB rows ----
            {
                const int acol = rowtab ? 0 : seg * 128;
                #pragma unroll
                for (int i = 0; i < 8; i++) {
                    int idx   = i * 256 + tid;          // 0..2047
                    int plane = idx >> 10;              // 0 hi, 1 lo
                    int r     = (idx >> 4) & 63;
                    int ch    = idx & 15;
                    int srow  = rowtab ? rowtab[(size_t)seg * M + brow + r] : (brow + r);
                    uint32_t dst = (plane ? A_LO : A_HI) + (uint32_t)(r * (TSTRIDE*2) + ch * 16);
                    const __nv_bfloat16* src = Aimg + (size_t)plane * Aplane
                                             + (size_t)(srow < 0 ? 0 : srow) * Krow + acol + ch * 8;
                    cp16z(dst, src, srow < 0 ? 0 : 16);
                }
            }
            // ---- B tile: 4096 16B chunks (only first tile; stays resident after) ----
            if (t == 0) {
                const __nv_bfloat16* Bseg = Bimg + ((size_t)(bx * nseg + seg)) * 32768;
                #pragma unroll
                for (int i = 0; i < 16; i++) {
                    int idx   = i * 256 + tid;          // 0..4095
                    int plane = idx >> 11;
                    int r     = (idx >> 4) & 127;
                    int ch    = idx & 15;
                    uint32_t dst = (plane ? B_LO : B_HI) + (uint32_t)(r * (TSTRIDE*2) + ch * 16);
                    cp16(dst, Bseg + plane * 16384 + r * 128 + ch * 8);
                }
            }
            CP_COMMIT();
            CP_WAIT0();
            __syncthreads();

            // ---- cached fragments; 3 passes from registers ----
            #pragma unroll
            for (int kc = 0; kc < 4; kc++) {
                uint32_t bh[4][4], bl[4][4];
                #pragma unroll
                for (int nt = 0; nt < 4; nt++) {
                    uint32_t boff = bAddr0 + nt*8*(TSTRIDE*2) + kc*64;
                    ldsm4(B_HI + boff, bh[nt][0], bh[nt][1], bh[nt][2], bh[nt][3]);
                    ldsm4(B_LO + boff, bl[nt][0], bl[nt][1], bl[nt][2], bl[nt][3]);
                }
                uint32_t ah[2][2][4], al[2][2][4];
                #pragma unroll
                for (int half = 0; half < 2; half++)
                    #pragma unroll
                    for (int mt = 0; mt < 2; mt++) {
                        uint32_t aoff = aAddr0 + mt*16*(TSTRIDE*2) + kc*64 + half*32;
                        ldsm4(A_HI + aoff, ah[half][mt][0], ah[half][mt][1], ah[half][mt][2], ah[half][mt][3]);
                        ldsm4(A_LO + aoff, al[half][mt][0], al[half][mt][1], al[half][mt][2], al[half][mt][3]);
                    }
                #pragma unroll
                for (int half = 0; half < 2; half++)
                    #pragma unroll
                    for (int mt = 0; mt < 2; mt++)
                        #pragma unroll
                        for (int nt = 0; nt < 4; nt++)
                            mma16816(acc[mt][nt], ah[half][mt], bh[nt][half*2], bh[nt][half*2+1]);
                #pragma unroll
                for (int half = 0; half < 2; half++)
                    #pragma unroll
                    for (int mt = 0; mt < 2; mt++)
                        #pragma unroll
                        for (int nt = 0; nt < 4; nt++)
                            mma16816(acc[mt][nt], ah[half][mt], bl[nt][half*2], bl[nt][half*2+1]);
                #pragma unroll
                for (int half = 0; half < 2; half++)
                    #pragma unroll
                    for (int mt = 0; mt < 2; mt++)
                        #pragma unroll
                        for (int nt = 0; nt < 4; nt++)
                            mma16816(acc[mt][nt], al[half][mt], bh[nt][half*2], bh[nt][half*2+1]);
            }
        }

        // ---- epilogue for this tile ----
        #pragma unroll
        for (int mt = 0; mt < 2; mt++) {
            int r0 = brow + rowbase + mt*16 + (lane >> 2);
            #pragma unroll
            for (int nt = 0; nt < 4; nt++) {
                int c = bcol + colbase + nt*8 + (lane & 3)*2;
                float v0 = acc[mt][nt][0], v1 = acc[mt][nt][1];
                float v2 = acc[mt][nt][2], v3 = acc[mt][nt][3];
                if (bias) {
                    float b0 = bias[c], b1 = bias[c+1];
                    v0 += b0; v1 += b1; v2 += b0; v3 += b1;
                }
                if (act) {
                    v0 = gelu_exact(v0); v1 = gelu_exact(v1);
                    v2 = gelu_exact(v2); v3 = gelu_exact(v3);
                }
                if (OutSplit) {
                    uint16_t* hi = (uint16_t*)OutSplit;
                    uint16_t* lo = hi + Oplane;
                    __nv_bfloat16 h0 = __float2bfloat16(v0), h1 = __float2bfloat16(v1);
                    __nv_bfloat16 h2 = __float2bfloat16(v2), h3 = __float2bfloat16(v3);
                    *(uint32_t*)(hi + (size_t)r0*ldc + c) =
                        (uint32_t)__bfloat16_as_ushort(h0) | ((uint32_t)__bfloat16_as_ushort(h1) << 16);
                    *(uint32_t*)(lo + (size_t)r0*ldc + c) =
                        packbf(v0 - __bfloat162float(h0), v1 - __bfloat162float(h1));
                    *(uint32_t*)(hi + (size_t)(r0+8)*ldc + c) =
                        (uint32_t)__bfloat16_as_ushort(h2) | ((uint32_t)__bfloat16_as_ushort(h3) << 16);
                    *(uint32_t*)(lo + (size_t)(r0+8)*ldc + c) =
                        packbf(v2 - __bfloat162float(h2), v3 - __bfloat162float(h3));
                } else {
                    *(float2*)(C + (size_t)r0 * ldc + c)     = make_float2(v0, v1);
                    *(float2*)(C + (size_t)(r0+8) * ldc + c) = make_float2(v2, v3);
                }
            }
        }
    }
}

// ---------------- standalone GEMM kernel (per-iteration ops) ----------------
__global__ __launch_bounds__(256, 2)
void tgemm2(int M, int Krow, int nseg, int mtiles,
            const __nv_bfloat16* __restrict__ Aimg, size_t Aplane,
            const int* __restrict__ rowtab,
            const __nv_bfloat16* __restrict__ Bimg,
            float* __restrict__ C, int ldc,
            const float* __restrict__ bias, int act,
            __nv_bfloat16* OutSplit, size_t Oplane)
{
    extern __shared__ char smem[];
    tgemm_body(smem, blockIdx.x, blockIdx.y, M, Krow, nseg, mtiles,
               Aimg, Aplane, rowtab, Bimg, C, ldc, bias, act, OutSplit, Oplane);
}

// ---------------- fused prologue: k (512 CTAs) + v (512 CTAs) + conv (256 CTAs) ----------------
__global__ __launch_bounds__(256, 2)
void tgemm_pro(const __nv_bfloat16* __restrict__ xl, const __nv_bfloat16* __restrict__ xr,
               const __nv_bfloat16* __restrict__ wimg, const int* __restrict__ rows,
               float* __restrict__ K, float* __restrict__ V, float* __restrict__ Seed)
{
    extern __shared__ char smem[];
    const size_t APL_BIG = (size_t)NTOKIN*DIMX;
    int cta = blockIdx.x;
    if (cta < 512) {
        tgemm_body(smem, 0, cta, NTOKIN, 128, 1, 2, xl, APL_BIG, 0,
                   wimg + 0*32768, K, 128, 0, 0, 0, 0);
    } else if (cta < 1024) {
        tgemm_body(smem, 0, cta - 512, NTOKIN, 128, 1, 2, xr, APL_BIG, 0,
                   wimg + 1*32768, V, 128, 0, 0, 0, 0);
    } else {
        tgemm_body(smem, 0, cta - 1024, NTOK, 128, 9, 1, xr, APL_BIG, rows,
                   wimg + 7*32768, Seed, 128, 0, 0, 0, 0);
    }
}

// ---------------- attention: dots + softmax + eps, atomic col sums ----------------
__global__ __launch_bounds__(128)
void attn_kernel(const float* __restrict__ Kv, const float* __restrict__ Qv,
                 const float* __restrict__ rpb, const float* __restrict__ tau,
                 float* __restrict__ attn_out, float* __restrict__ colsums)
{
    int bp = blockIdx.x;
    int b = bp >> 12, p = bp & 4095;
    int h = p >> 6, w = p & 63;
    int hc = min(max(h,1),62), wc = min(max(w,1),62);

    __shared__ __align__(16) float q_sh[9][128];
    int tid = threadIdx.x;
    #pragma unroll
    for (int t = 0; t < 9; t++) {
        int np = (hc + t/3 - 1)*64 + (wc + t%3 - 1);
        q_sh[t][tid] = Qv[((size_t)(b<<12) + np)*DIMX + tid];
    }
    __syncthreads();

    int g = tid >> 5, lane = tid & 31;
    int tin = (2*h + (g>>1))*128 + 2*w + (g&1);
    float4 kv = *(const float4*)(Kv + ((size_t)(b*16384 + tin))*DIMX + lane*4);

    float myd = 0.0f;
    #pragma unroll
    for (int t = 0; t < 9; t++) {
        float4 qv = *(const float4*)(&q_sh[t][lane*4]);
        float d = kv.x*qv.x + kv.y*qv.y + kv.z*qv.z + kv.w*qv.w;
        #pragma unroll
        for (int o = 16; o > 0; o >>= 1) d += __shfl_xor_sync(0xffffffffu, d, o);
        if (lane == t) myd = d;
    }

    float scale = expf(*tau);
    float z = (lane < 9) ? (myd + rpb[g*9 + lane]) * scale : -1e30f;
    float m = z;
    #pragma unroll
    for (int o = 16; o > 0; o >>= 1) m = fmaxf(m, __shfl_xor_sync(0xffffffffu, m, o));
    float e = (lane < 9) ? expf(z - m) : 0.0f;
    float s = e;
    #pragma unroll
    for (int o = 16; o > 0; o >>= 1) s += __shfl_xor_sync(0xffffffffu, s, o);

    if (lane < 9) {
        float a = e / s + 1e-6f;
        attn_out[(((size_t)(b*4 + g))*4096 + p)*9 + lane] = a;
        int np = (hc + lane/3 - 1)*64 + (wc + lane%3 - 1);
        atomicAdd(&colsums[(b<<12) + np], a);
    }
}

// ---------------- column-normalize + weighted v gather; x_out += upd; raw split out ----
__global__ __launch_bounds__(128)
void upd_kernel(const float* __restrict__ attn_out, const float* __restrict__ colsums,
                const float* __restrict__ Vv, float* __restrict__ acol_out,
                float* __restrict__ x_out)
{
    int bp = blockIdx.x;
    int b = bp >> 12, p = bp & 4095;
    int h = p >> 6, w = p & 63;
    int hc = min(max(h,1),62), wc = min(max(w,1),62);

    __shared__ float sA[36];
    int tid = threadIdx.x;
    if (tid < 36) {
        int g = tid / 9, t = tid % 9;
        float a  = attn_out[(((size_t)(b*4 + g))*4096 + p)*9 + t];
        int np   = (hc + t/3 - 1)*64 + (wc + t%3 - 1);
        float cs = colsums[(b<<12) + np];
        float val = a / (cs + 1e-8f);
        sA[tid] = val;
        acol_out[(((size_t)(b*4 + g))*4096 + p)*9 + t] = val;
    }
    __syncthreads();

    float acc = 0.0f;
    #pragma unroll
    for (int g = 0; g < 4; g++) {
        #pragma unroll
        for (int t = 0; t < 9; t++) {
            int nh = hc + t/3 - 1, nw = wc + t%3 - 1;
            int tin = (2*nh + (g>>1))*128 + 2*nw + (g&1);
            acc += sA[g*9 + t] * Vv[((size_t)(b*16384 + tin))*DIMX + tid];
        }
    }
    size_t idx = ((size_t)(b<<12) + p)*DIMX + tid;
    float nv = x_out[idx] + acc;
    x_out[idx] = nv;
    __nv_bfloat16 hi = __float2bfloat16(nv);
    ((uint16_t*)g_xor_)[idx] = __bfloat16_as_ushort(hi);
    ((uint16_t*)g_xor_)[(size_t)NTOK*DIMX + idx] =
        __bfloat16_as_ushort(__float2bfloat16(nv - __bfloat162float(hi)));
}

// ---------------- launcher ----------------
extern "C" void kernel_launch(void* const* d_in, const int* in_sizes, int n_in,
                              void* d_out, int out_size)
{
    (void)in_sizes; (void)n_in; (void)out_size;
    const float* x        = (const float*)d_in[0];
    const float* conv_w   = (const float*)d_in[1];
    const float* q_w      = (const float*)d_in[2];
    const float* k_w      = (const float*)d_in[3];
    const float* v_w      = (const float*)d_in[4];
    const float* mlp_w1   = (const float*)d_in[5];
    const float* mlp_b1   = (const float*)d_in[6];
    const float* mlp_w2   = (const float*)d_in[7];
    const float* mlp_b2   = (const float*)d_in[8];
    const float* ln_in_g  = (const float*)d_in[9];
    const float* ln_in_b  = (const float*)d_in[10];
    const float* ln_out_g = (const float*)d_in[11];
    const float* ln_out_b = (const float*)d_in[12];
    const float* tau      = (const float*)d_in[13];
    const float* rpb      = (const float*)d_in[14];

    float* xout     = (float*)d_out;
    float* attn_out = xout + (size_t)NTOK * DIMX;
    float* acol_out = attn_out + (size_t)BATCH * 4 * NP * 9;

    float *p_k, *p_v, *p_q, *p_seed, *p_h2, *p_cs;
    __nv_bfloat16 *p_wimg, *p_xr, *p_xl, *p_xor, *p_xol, *p_hb;
    int* p_rows;
    cudaGetSymbolAddress((void**)&p_k,   g_k);
    cudaGetSymbolAddress((void**)&p_v,   g_v);
    cudaGetSymbolAddress((void**)&p_q,   g_q);
    cudaGetSymbolAddress((void**)&p_seed,g_seed);
    cudaGetSymbolAddress((void**)&p_h2,  g_h2);
    cudaGetSymbolAddress((void**)&p_cs,  g_cs);
    cudaGetSymbolAddress((void**)&p_wimg,g_wimg);
    cudaGetSymbolAddress((void**)&p_xr,  g_xr);
    cudaGetSymbolAddress((void**)&p_xl,  g_xl);
    cudaGetSymbolAddress((void**)&p_xor, g_xor_);
    cudaGetSymbolAddress((void**)&p_xol, g_xol);
    cudaGetSymbolAddress((void**)&p_hb,  g_hb);
    cudaGetSymbolAddress((void**)&p_rows,g_rows);

    static int attr_set = 0;
    if (!attr_set) {
        cudaFuncSetAttribute(tgemm2,    cudaFuncAttributeMaxDynamicSharedMemorySize, TG_SMEM);
        cudaFuncSetAttribute(tgemm_pro, cudaFuncAttributeMaxDynamicSharedMemorySize, TG_SMEM);
        attr_set = 1;
    }

    const size_t APL_TOK = (size_t)NTOK*DIMX;
    const size_t APL_H   = (size_t)NTOK*2*DIMX;

    // prep
    prep_conv<<<(9*NTOK + 255)/256, 256>>>(conv_w);
    prep_img<<<dim3(64, 16), 256>>>(k_w, v_w, q_w, mlp_w1, mlp_w2);
    split_x<<<NTOKIN/8, 256>>>(x, ln_in_g, ln_in_b);
    // fused prologue: k (mtiles=2) + v (mtiles=2) + conv (9 segs) in one 1280-CTA launch
    tgemm_pro<<<1280, 256, TG_SMEM>>>(p_xl, p_xr, p_wimg, p_rows, p_k, p_v, p_seed);
    // x_out = LN(seed); also emits LN(xout) split for q
    ln2_kernel<<<NTOK/8, 256>>>(p_seed, xout, ln_out_g, ln_out_b, 0);

    for (int it = 0; it < 3; it++) {
        // q = LN_out(xout) @ q_w (mtiles=1: keep 256-CTA grid fill)
        tgemm2<<<dim3(1, NTOK/64), 256, TG_SMEM>>>(NTOK, 128, 1, 1, p_xol, APL_TOK, 0, p_wimg + 2*32768, p_q, 128, 0, 0, 0, 0);
        cudaMemsetAsync(p_cs, 0, NTOK * sizeof(float));
        attn_kernel<<<NTOK, 128>>>(p_k, p_q, rpb, tau, attn_out, p_cs);
        upd_kernel<<<NTOK, 128>>>(attn_out, p_cs, p_v, acol_out, xout);
        // mlp1: h = gelu(xout @ w1 + b1), pre-split output (mtiles=2 -> 256 CTAs)
        tgemm2<<<dim3(2, NTOK/128), 256, TG_SMEM>>>(NTOK, 128, 1, 2, p_xor, APL_TOK, 0, p_wimg + 3*32768, 0, 256, mlp_b1, 1, p_hb, APL_H);
        // mlp2: h2 = h @ w2 + b2 (2 K-segments, mtiles=1)
        tgemm2<<<dim3(1, NTOK/64), 256, TG_SMEM>>>(NTOK, 256, 2, 1, p_hb, APL_H, 0, p_wimg + 5*32768, p_h2, 128, mlp_b2, 0, 0, 0);
        // xout += LN(h2); emits LN(xout) split
        ln2_kernel<<<NTOK/8, 256>>>(p_h2, xout, ln_out_g, ln_out_b, 1);
    }
}